// round 4
// baseline (speedup 1.0000x reference)
#include <cuda_runtime.h>
#include <cuda_bf16.h>
#include <math.h>

// VGAE decoder = 3-layer GCN.
//   deg = segsum(ew, col) + 1 ; dinv = rsqrt(deg)
//   norm_e = dinv[row]*ew*dinv[col] ; norm_self = dinv*dinv
//   layer(h,W,b): A(hW) + b  where A = offdiag(norm_e) + diag(norm_self)
// Identity: A(hW) = (Ah)W, so layer1 aggregates in 64-dim input space.
// Aggregation is atomic-free via a CSC edge list built per launch.
// edge_index dtype is detected at runtime (int32 vs int64) — reading int32
// data as int64 produces wild addresses -> error 717. Indices are also
// bounds-guarded so a wrong assumption shows up as rel_err, not a trap.

#define NMAX 100000
#define EMAX 1600000
#define SCAN_B 1024

// ---------------- device scratch -------------------------------------------
__device__ int   g_is64;
__device__ float g_deg[NMAX];
__device__ float g_dinv[NMAX];
__device__ int   g_cnt[NMAX];
__device__ int   g_off[NMAX];
__device__ int   g_cur[NMAX];
__device__ int   g_bsum[128];
__device__ int   g_bpre[128];
__device__ int   g_src[EMAX];
__device__ float g_wn[EMAX];
__device__ __align__(16) float g_bufA[(size_t)NMAX * 128];
__device__ __align__(16) float g_bufB[(size_t)NMAX * 128];

// compile-time buffer selector: 0 = passed pointer, 1 = g_bufA, 2 = g_bufB
template<int SEL>
__device__ __forceinline__ const float* sel_src(const float* p) {
    if (SEL == 1) return g_bufA;
    if (SEL == 2) return g_bufB;
    return p;
}
template<int SEL>
__device__ __forceinline__ float* sel_dst(float* p) {
    if (SEL == 1) return g_bufA;
    if (SEL == 2) return g_bufB;
    return p;
}

// ---------------- dtype detection ------------------------------------------
__global__ void init_flag() { g_is64 = 1; }

// If edge_index is int64 (values < 2^31, little-endian), every odd 32-bit
// word is 0. If it's int32 (uniform values in [0,N)), some odd word != 0.
__global__ void detect32(const int* __restrict__ ei32, int E) {
    int e = blockIdx.x * blockDim.x + threadIdx.x;
    if (e < E && ei32[2 * e + 1] != 0) g_is64 = 0;
}

template<bool IS64>
__device__ __forceinline__ int edge_at(const void* eiv, size_t idx) {
    if (IS64) return (int)((const long long*)eiv)[idx];
    return ((const int*)eiv)[idx];
}

// ---------------- preprocessing kernels ------------------------------------
__global__ void init_nodes(int n) {
    int i = blockIdx.x * blockDim.x + threadIdx.x;
    if (i < n) { g_deg[i] = 1.0f; g_cnt[i] = 0; g_cur[i] = 0; }
}

template<bool IS64>
__global__ void edge_deg(const void* __restrict__ eiv,
                         const float* __restrict__ ew, int E, int n) {
    if (g_is64 != (IS64 ? 1 : 0)) return;
    int e = blockIdx.x * blockDim.x + threadIdx.x;
    if (e >= E) return;
    int c = edge_at<IS64>(eiv, (size_t)E + e);
    if ((unsigned)c >= (unsigned)n) return;   // guard: wrong dtype -> rel_err, not trap
    atomicAdd(&g_deg[c], ew[e]);
    atomicAdd(&g_cnt[c], 1);
}

__global__ void node_dinv(int n) {
    int i = blockIdx.x * blockDim.x + threadIdx.x;
    if (i < n) g_dinv[i] = rsqrtf(g_deg[i]);
}

// three-phase exclusive scan of g_cnt -> g_off
__global__ void scan_blocks(int n) {
    __shared__ int s[SCAN_B];
    int t = threadIdx.x;
    int i = blockIdx.x * SCAN_B + t;
    int v = (i < n) ? g_cnt[i] : 0;
    s[t] = v;
    __syncthreads();
    for (int o = 1; o < SCAN_B; o <<= 1) {
        int x = (t >= o) ? s[t - o] : 0;
        __syncthreads();
        s[t] += x;
        __syncthreads();
    }
    if (i < n) g_off[i] = s[t] - v;
    if (t == SCAN_B - 1) g_bsum[blockIdx.x] = s[t];
}

__global__ void scan_sums(int nb) {
    if (threadIdx.x == 0 && blockIdx.x == 0) {
        int run = 0;
        for (int b = 0; b < nb; b++) { int t = g_bsum[b]; g_bpre[b] = run; run += t; }
    }
}

__global__ void scan_add(int n) {
    int i = blockIdx.x * blockDim.x + threadIdx.x;
    if (i < n) g_off[i] += g_bpre[i >> 10];
}

template<bool IS64>
__global__ void edge_scatter(const void* __restrict__ eiv,
                             const float* __restrict__ ew, int E, int n) {
    if (g_is64 != (IS64 ? 1 : 0)) return;
    int e = blockIdx.x * blockDim.x + threadIdx.x;
    if (e >= E) return;
    int r = edge_at<IS64>(eiv, e);
    int c = edge_at<IS64>(eiv, (size_t)E + e);
    if ((unsigned)r >= (unsigned)n || (unsigned)c >= (unsigned)n) return;  // guard
    float wn = g_dinv[r] * ew[e] * g_dinv[c];
    int p = g_off[c] + atomicAdd(&g_cur[c], 1);
    g_src[p] = r;
    g_wn[p]  = wn;
}

// ---------------- gather: out[n] = sum_e wn*T[src] + dinv^2*T[n] (+b)(sig) --
template<int M, int SSEL, int DSEL, bool BIAS, bool SIG>
__global__ void gather_kernel(const float* __restrict__ Tp,
                              const float* __restrict__ bias,
                              float* __restrict__ outp, int n) {
    const float* T = sel_src<SSEL>(Tp);
    float* out = sel_dst<DSEL>(outp);
    constexpr int G = 256 / M;
    int node = blockIdx.x * G + threadIdx.y;
    if (node >= n) return;
    int m = threadIdx.x;
    int start = g_off[node];
    int cnt   = g_cnt[node];
    float acc = 0.0f;
    // 2-deep pipeline on edge metadata to shorten the dependent chain
    int   s0 = 0; float w0 = 0.0f;
    if (cnt > 0) { s0 = g_src[start]; w0 = g_wn[start]; }
    for (int i = 0; i < cnt - 1; i++) {
        int   s1 = g_src[start + i + 1];
        float w1 = g_wn[start + i + 1];
        acc += w0 * T[(size_t)s0 * M + m];
        s0 = s1; w0 = w1;
    }
    if (cnt > 0) acc += w0 * T[(size_t)s0 * M + m];
    float di = g_dinv[node];
    acc += di * di * T[(size_t)node * M + m];
    if (BIAS) acc += bias[m];
    if (SIG)  acc = 1.0f / (1.0f + expf(-acc));
    out[(size_t)node * M + m] = acc;
}

// ---------------- GEMM: out[N,M] = A[N,K] @ W[K,M] (+b) --------------------
// Block tile 64 rows x M cols. Thread tile 8 rows x 4 cols.
template<int K, int M, int SSEL, int DSEL, bool BIAS>
__global__ void __launch_bounds__(256)
gemm_kernel(const float* __restrict__ Ap, const float* __restrict__ W,
            const float* __restrict__ bias, float* __restrict__ outp, int n) {
    const float* A = sel_src<SSEL>(Ap);
    float* out = sel_dst<DSEL>(outp);
    constexpr int BR = 64, KC = 32;
    constexpr int TX = M / 4, TY = 8;
    __shared__ float sW[K * M];
    __shared__ float sA[BR * KC];   // [r][k], stride KC
    int tx = threadIdx.x, ty = threadIdx.y;
    int tid = ty * TX + tx;
    constexpr int NTH = TX * TY;
    for (int i = tid; i < K * M; i += NTH) sW[i] = W[i];

    int row0 = blockIdx.x * BR;
    float acc[8][4];
#pragma unroll
    for (int r = 0; r < 8; r++)
#pragma unroll
        for (int c = 0; c < 4; c++) acc[r][c] = 0.0f;

    for (int kc = 0; kc < K; kc += KC) {
        __syncthreads();
        for (int i = tid; i < BR * KC; i += NTH) {
            int r = i / KC, k = i % KC;
            int gr = row0 + r;
            sA[i] = (gr < n) ? A[(size_t)gr * K + kc + k] : 0.0f;
        }
        __syncthreads();
#pragma unroll
        for (int k = 0; k < KC; k++) {
            float4 b4 = *(const float4*)&sW[(kc + k) * M + tx * 4];
#pragma unroll
            for (int r = 0; r < 8; r++) {
                float a = sA[(ty * 8 + r) * KC + k];
                acc[r][0] += a * b4.x;
                acc[r][1] += a * b4.y;
                acc[r][2] += a * b4.z;
                acc[r][3] += a * b4.w;
            }
        }
    }

    float4 bb = make_float4(0.f, 0.f, 0.f, 0.f);
    if (BIAS) bb = *(const float4*)&bias[tx * 4];
#pragma unroll
    for (int r = 0; r < 8; r++) {
        int gr = row0 + ty * 8 + r;
        if (gr < n) {
            float4 v;
            v.x = acc[r][0] + bb.x;
            v.y = acc[r][1] + bb.y;
            v.z = acc[r][2] + bb.z;
            v.w = acc[r][3] + bb.w;
            *(float4*)&out[(size_t)gr * M + tx * 4] = v;
        }
    }
}

// ---------------- launch ----------------------------------------------------
extern "C" void kernel_launch(void* const* d_in, const int* in_sizes, int n_in,
                              void* d_out, int out_size) {
    const float* x  = (const float*)d_in[0];
    const void*  ei = d_in[1];
    const float* ew = (const float*)d_in[2];
    const float* W1 = (const float*)d_in[3];
    const float* b1 = (const float*)d_in[4];
    const float* W2 = (const float*)d_in[5];
    const float* b2 = (const float*)d_in[6];
    const float* W3 = (const float*)d_in[7];
    const float* b3 = (const float*)d_in[8];
    float* out = (float*)d_out;

    int N = in_sizes[0] / 64;
    int E = in_sizes[1] / 2;

    int nb256_n = (N + 255) / 256;
    int nb256_e = (E + 255) / 256;
    int nbscan  = (N + SCAN_B - 1) / SCAN_B;

    // dtype detection for edge_index (int32 vs int64)
    init_flag<<<1, 1>>>();
    detect32<<<nb256_e, 256>>>((const int*)ei, E);

    // preprocessing: degree, dinv, CSC build
    init_nodes<<<nb256_n, 256>>>(N);
    edge_deg<false><<<nb256_e, 256>>>(ei, ew, E, N);
    edge_deg<true><<<nb256_e, 256>>>(ei, ew, E, N);
    node_dinv<<<nb256_n, 256>>>(N);
    scan_blocks<<<nbscan, SCAN_B>>>(N);
    scan_sums<<<1, 32>>>(nbscan);
    scan_add<<<nb256_n, 256>>>(N);
    edge_scatter<false><<<nb256_e, 256>>>(ei, ew, E, N);
    edge_scatter<true><<<nb256_e, 256>>>(ei, ew, E, N);

    // layer 1 (aggregate-first in 64-dim): G = A x -> bufA ; H1 = G@W1+b1 -> bufB
    gather_kernel<64, 0, 1, false, false><<<(N + 3) / 4, dim3(64, 4)>>>(x, nullptr, nullptr, N);
    gemm_kernel<64, 128, 1, 2, true><<<(N + 63) / 64, dim3(32, 8)>>>(nullptr, W1, b1, nullptr, N);

    // layer 2: T2 = H1@W2 -> bufA ; H2 = A T2 + b2 -> bufB
    gemm_kernel<128, 64, 2, 1, false><<<(N + 63) / 64, dim3(16, 8)>>>(nullptr, W2, nullptr, nullptr, N);
    gather_kernel<64, 1, 2, true, false><<<(N + 3) / 4, dim3(64, 4)>>>(nullptr, b2, nullptr, N);

    // layer 3: T3 = H2@W3 -> bufA ; out = sigmoid(A T3 + b3)
    gemm_kernel<64, 32, 2, 1, false><<<(N + 63) / 64, dim3(8, 8)>>>(nullptr, W3, nullptr, nullptr, N);
    gather_kernel<32, 1, 0, true, true><<<(N + 7) / 8, dim3(32, 8)>>>(nullptr, b3, out, N);

    (void)n_in; (void)out_size;
}

// round 5
// speedup vs baseline: 1.3497x; 1.3497x over previous
#include <cuda_runtime.h>
#include <cuda_bf16.h>
#include <math.h>

// VGAE decoder = 3-layer GCN. See R0-R4 notes.
//   layer(h,W,b): A(hW) + b ; A(hW) = (Ah)W so layer1 aggregates in 64-dim.
// Gather order chosen so gather dims are 64/64/32 (minimal).
// edge_index confirmed int32 (R4 ncu evidence); bounds guards keep any
// surprise visible as rel_err instead of a trap.

#define NMAX 100000
#define EMAX 1600000
#define SCAN_B 1024

// ---------------- device scratch -------------------------------------------
__device__ float g_deg[NMAX];
__device__ float g_dinv[NMAX];
__device__ int   g_cnt[NMAX];
__device__ int   g_off[NMAX];
__device__ int   g_cur[NMAX];
__device__ int   g_bsum[128];
__device__ int   g_bpre[128];
__device__ __align__(8)  int2  g_edge[EMAX];          // packed {src, wn-bits}
__device__ __align__(16) float g_bufA[(size_t)NMAX * 128];
__device__ __align__(16) float g_bufB[(size_t)NMAX * 128];

template<int SEL>
__device__ __forceinline__ const float* sel_src(const float* p) {
    if (SEL == 1) return g_bufA;
    if (SEL == 2) return g_bufB;
    return p;
}
template<int SEL>
__device__ __forceinline__ float* sel_dst(float* p) {
    if (SEL == 1) return g_bufA;
    if (SEL == 2) return g_bufB;
    return p;
}

// ---------------- preprocessing kernels ------------------------------------
__global__ void init_nodes(int n) {
    int i = blockIdx.x * blockDim.x + threadIdx.x;
    if (i < n) { g_deg[i] = 1.0f; g_cnt[i] = 0; }
}

__global__ void edge_deg(const int* __restrict__ ei,
                         const float* __restrict__ ew, int E, int n) {
    int e = blockIdx.x * blockDim.x + threadIdx.x;
    if (e >= E) return;
    int c = ei[E + e];
    if ((unsigned)c >= (unsigned)n) return;   // guard
    atomicAdd(&g_deg[c], ew[e]);
    atomicAdd(&g_cnt[c], 1);
}

__global__ void node_dinv(int n) {
    int i = blockIdx.x * blockDim.x + threadIdx.x;
    if (i < n) g_dinv[i] = rsqrtf(g_deg[i]);
}

// three-phase exclusive scan of g_cnt -> g_off (+ copy to g_cur)
__global__ void scan_blocks(int n) {
    __shared__ int s[SCAN_B];
    int t = threadIdx.x;
    int i = blockIdx.x * SCAN_B + t;
    int v = (i < n) ? g_cnt[i] : 0;
    s[t] = v;
    __syncthreads();
    for (int o = 1; o < SCAN_B; o <<= 1) {
        int x = (t >= o) ? s[t - o] : 0;
        __syncthreads();
        s[t] += x;
        __syncthreads();
    }
    if (i < n) g_off[i] = s[t] - v;
    if (t == SCAN_B - 1) g_bsum[blockIdx.x] = s[t];
}

__global__ void scan_sums(int nb) {
    if (threadIdx.x == 0 && blockIdx.x == 0) {
        int run = 0;
        for (int b = 0; b < nb; b++) { int t = g_bsum[b]; g_bpre[b] = run; run += t; }
    }
}

__global__ void scan_add(int n) {
    int i = blockIdx.x * blockDim.x + threadIdx.x;
    if (i < n) {
        int o = g_off[i] + g_bpre[i >> 10];
        g_off[i] = o;
        g_cur[i] = o;   // scatter bumps g_cur directly
    }
}

__global__ void edge_scatter(const int* __restrict__ ei,
                             const float* __restrict__ ew, int E, int n) {
    int e = blockIdx.x * blockDim.x + threadIdx.x;
    if (e >= E) return;
    int r = ei[e];
    int c = ei[E + e];
    if ((unsigned)r >= (unsigned)n || (unsigned)c >= (unsigned)n) return;  // guard
    float wn = g_dinv[r] * ew[e] * g_dinv[c];
    int p = atomicAdd(&g_cur[c], 1);
    g_edge[p] = make_int2(r, __float_as_int(wn));
}

// ---------------- gather: out[n] = sum_e wn*T[src] + dinv^2*T[n] (+b)(sig) --
// float4 lanes: L = M/4 threads per node; 4-deep edge unroll for MLP.
template<int M, int SSEL, int DSEL, bool BIAS, bool SIG>
__global__ void __launch_bounds__(256)
gather4_kernel(const float* __restrict__ Tp,
               const float* __restrict__ bias,
               float* __restrict__ outp, int n) {
    constexpr int L = M / 4;                 // float4 lanes per node
    const float4* T = (const float4*)sel_src<SSEL>(Tp);
    float4* out = (float4*)sel_dst<DSEL>(outp);
    int node = blockIdx.x * (256 / L) + threadIdx.y;
    if (node >= n) return;
    int m = threadIdx.x;                     // 0..L-1
    int start = g_off[node];
    int cnt   = g_cnt[node];

    float ax = 0.f, ay = 0.f, az = 0.f, aw = 0.f;
    int i = 0;
    for (; i + 4 <= cnt; i += 4) {
        int2 e0 = g_edge[start + i];
        int2 e1 = g_edge[start + i + 1];
        int2 e2 = g_edge[start + i + 2];
        int2 e3 = g_edge[start + i + 3];
        float4 t0 = T[(size_t)e0.x * L + m];
        float4 t1 = T[(size_t)e1.x * L + m];
        float4 t2 = T[(size_t)e2.x * L + m];
        float4 t3 = T[(size_t)e3.x * L + m];
        float w0 = __int_as_float(e0.y), w1 = __int_as_float(e1.y);
        float w2 = __int_as_float(e2.y), w3 = __int_as_float(e3.y);
        ax += w0 * t0.x; ay += w0 * t0.y; az += w0 * t0.z; aw += w0 * t0.w;
        ax += w1 * t1.x; ay += w1 * t1.y; az += w1 * t1.z; aw += w1 * t1.w;
        ax += w2 * t2.x; ay += w2 * t2.y; az += w2 * t2.z; aw += w2 * t2.w;
        ax += w3 * t3.x; ay += w3 * t3.y; az += w3 * t3.z; aw += w3 * t3.w;
    }
    for (; i < cnt; i++) {
        int2 e0 = g_edge[start + i];
        float4 t0 = T[(size_t)e0.x * L + m];
        float w0 = __int_as_float(e0.y);
        ax += w0 * t0.x; ay += w0 * t0.y; az += w0 * t0.z; aw += w0 * t0.w;
    }
    float di = g_dinv[node];
    float ns = di * di;
    float4 ts = T[(size_t)node * L + m];
    ax += ns * ts.x; ay += ns * ts.y; az += ns * ts.z; aw += ns * ts.w;
    if (BIAS) {
        float4 bb = ((const float4*)bias)[m];
        ax += bb.x; ay += bb.y; az += bb.z; aw += bb.w;
    }
    if (SIG) {
        ax = 1.0f / (1.0f + __expf(-ax));
        ay = 1.0f / (1.0f + __expf(-ay));
        az = 1.0f / (1.0f + __expf(-az));
        aw = 1.0f / (1.0f + __expf(-aw));
    }
    out[(size_t)node * L + m] = make_float4(ax, ay, az, aw);
}

// ---------------- GEMM: out[N,M] = A[N,K] @ W[K,M] (+b) --------------------
template<int K, int M, int SSEL, int DSEL, bool BIAS>
__global__ void __launch_bounds__(256)
gemm_kernel(const float* __restrict__ Ap, const float* __restrict__ W,
            const float* __restrict__ bias, float* __restrict__ outp, int n) {
    const float* A = sel_src<SSEL>(Ap);
    float* out = sel_dst<DSEL>(outp);
    constexpr int BR = 64, KC = 32;
    constexpr int TX = M / 4, TY = 8;
    __shared__ float sW[K * M];
    __shared__ float sA[BR * KC];   // [r][k], stride KC
    int tx = threadIdx.x, ty = threadIdx.y;
    int tid = ty * TX + tx;
    constexpr int NTH = TX * TY;
    for (int i = tid; i < K * M; i += NTH) sW[i] = W[i];

    int row0 = blockIdx.x * BR;
    float acc[8][4];
#pragma unroll
    for (int r = 0; r < 8; r++)
#pragma unroll
        for (int c = 0; c < 4; c++) acc[r][c] = 0.0f;

    for (int kc = 0; kc < K; kc += KC) {
        __syncthreads();
        for (int i = tid; i < BR * KC; i += NTH) {
            int r = i / KC, k = i % KC;
            int gr = row0 + r;
            sA[i] = (gr < n) ? A[(size_t)gr * K + kc + k] : 0.0f;
        }
        __syncthreads();
#pragma unroll
        for (int k = 0; k < KC; k++) {
            float4 b4 = *(const float4*)&sW[(kc + k) * M + tx * 4];
#pragma unroll
            for (int r = 0; r < 8; r++) {
                float a = sA[(ty * 8 + r) * KC + k];
                acc[r][0] += a * b4.x;
                acc[r][1] += a * b4.y;
                acc[r][2] += a * b4.z;
                acc[r][3] += a * b4.w;
            }
        }
    }

    float4 bb = make_float4(0.f, 0.f, 0.f, 0.f);
    if (BIAS) bb = *(const float4*)&bias[tx * 4];
#pragma unroll
    for (int r = 0; r < 8; r++) {
        int gr = row0 + ty * 8 + r;
        if (gr < n) {
            float4 v;
            v.x = acc[r][0] + bb.x;
            v.y = acc[r][1] + bb.y;
            v.z = acc[r][2] + bb.z;
            v.w = acc[r][3] + bb.w;
            *(float4*)&out[(size_t)gr * M + tx * 4] = v;
        }
    }
}

// ---------------- launch ----------------------------------------------------
extern "C" void kernel_launch(void* const* d_in, const int* in_sizes, int n_in,
                              void* d_out, int out_size) {
    const float* x  = (const float*)d_in[0];
    const int*   ei = (const int*)d_in[1];
    const float* ew = (const float*)d_in[2];
    const float* W1 = (const float*)d_in[3];
    const float* b1 = (const float*)d_in[4];
    const float* W2 = (const float*)d_in[5];
    const float* b2 = (const float*)d_in[6];
    const float* W3 = (const float*)d_in[7];
    const float* b3 = (const float*)d_in[8];
    float* out = (float*)d_out;

    int N = in_sizes[0] / 64;
    int E = in_sizes[1] / 2;

    int nb256_n = (N + 255) / 256;
    int nb256_e = (E + 255) / 256;
    int nbscan  = (N + SCAN_B - 1) / SCAN_B;

    // preprocessing: degree, dinv, CSC build
    init_nodes<<<nb256_n, 256>>>(N);
    edge_deg<<<nb256_e, 256>>>(ei, ew, E, N);
    node_dinv<<<nb256_n, 256>>>(N);
    scan_blocks<<<nbscan, SCAN_B>>>(N);
    scan_sums<<<1, 32>>>(nbscan);
    scan_add<<<nb256_n, 256>>>(N);
    edge_scatter<<<nb256_e, 256>>>(ei, ew, E, N);

    // layer 1 (aggregate-first): G = A x -> bufA ; H1 = G@W1+b1 -> bufB
    gather4_kernel<64, 0, 1, false, false><<<(N + 15) / 16, dim3(16, 16)>>>(x, nullptr, nullptr, N);
    gemm_kernel<64, 128, 1, 2, true><<<(N + 63) / 64, dim3(32, 8)>>>(nullptr, W1, b1, nullptr, N);

    // layer 2: T2 = H1@W2 -> bufA ; H2 = A T2 + b2 -> bufB
    gemm_kernel<128, 64, 2, 1, false><<<(N + 63) / 64, dim3(16, 8)>>>(nullptr, W2, nullptr, nullptr, N);
    gather4_kernel<64, 1, 2, true, false><<<(N + 15) / 16, dim3(16, 16)>>>(nullptr, b2, nullptr, N);

    // layer 3: T3 = H2@W3 -> bufA ; out = sigmoid(A T3 + b3)
    gemm_kernel<64, 32, 2, 1, false><<<(N + 63) / 64, dim3(8, 8)>>>(nullptr, W3, nullptr, nullptr, N);
    gather4_kernel<32, 1, 0, true, true><<<(N + 31) / 32, dim3(8, 32)>>>(nullptr, b3, out, N);

    (void)n_in; (void)out_size;
}